// round 5
// baseline (speedup 1.0000x reference)
#include <cuda_runtime.h>
#include <cstdint>

// NeiAttention persistent mma.sync tf32, 512-thread CTAs (4 warps/SMSP).
// B=512,N=32,S=16,EF=64,NF=D=128,K=192. tile = 128 GEMM rows.
// W resident (pair-permuted tf32), A double-buffered raw via cp.async + in-place cvt pass,
// register-only attention epilogue.

#define NTILES 2048
#define NCTAS  148
#define WST    200     // W row stride: LDS.64 B-frags conflict-free (bank 8g+2t4)
#define AST    100     // A row stride: LDS.32 A-frags conflict-free (bank 4g+t4)

// smem layout (floats)
#define OFF_W    0        // 128*200 = 25600
#define OFF_A0   25600    // 128*100 = 12800
#define OFF_A1   38400    // 12800
#define OFF_X    51200    // 2 x 1024
#define OFF_PART 53248    // 512
#define OFF_AL   53760    // 128
#define OFF_E    53888    // 128
#define OFF_BIA  54016    // 128
#define SMEM_FLOATS 54144
#define SMEM_BYTES  (SMEM_FLOATS * 4)   // 216,576 B

__device__ __forceinline__ uint32_t smem_u32(const void* p) {
    uint32_t a;
    asm("{ .reg .u64 t; cvta.to.shared.u64 t, %1; cvt.u32.u64 %0, t; }" : "=r"(a) : "l"(p));
    return a;
}
__device__ __forceinline__ uint32_t cvt_tf32(float f) {
    uint32_t o; asm("cvt.rna.tf32.f32 %0, %1;" : "=r"(o) : "f"(f)); return o;
}
__device__ __forceinline__ void mma_tf32(float d[4], uint32_t a0, uint32_t a1,
                                         uint32_t a2, uint32_t a3,
                                         uint32_t b0, uint32_t b1) {
    asm volatile(
        "mma.sync.aligned.m16n8k8.row.col.f32.tf32.tf32.f32 "
        "{%0,%1,%2,%3}, {%4,%5,%6,%7}, {%8,%9}, {%0,%1,%2,%3};"
        : "+f"(d[0]), "+f"(d[1]), "+f"(d[2]), "+f"(d[3])
        : "r"(a0), "r"(a1), "r"(a2), "r"(a3), "r"(b0), "r"(b1));
}
__device__ __forceinline__ void cpa16(uint32_t dst, const void* src) {
    asm volatile("cp.async.cg.shared.global [%0], [%1], 16;" :: "r"(dst), "l"(src));
}
__device__ __forceinline__ void cp_commit() { asm volatile("cp.async.commit_group;" ::: "memory"); }
__device__ __forceinline__ void cp_wait_all() { asm volatile("cp.async.wait_group 0;" ::: "memory"); }
__device__ __forceinline__ float shflx(float v, int m) { return __shfl_xor_sync(0xffffffffu, v, m); }

// ---- raw staging via cp.async (fp32) ----
// half0: k 0..95 = rel[0..63] + nod[0..31]
__device__ __forceinline__ void stage_h0(uint32_t aU, const float* __restrict__ rel,
                                         const float* __restrict__ nod, int tile, int tid) {
    const float4* rp = (const float4*)(rel + (size_t)tile * 8192);
    #pragma unroll
    for (int it = 0; it < 4; it++) {
        int idx = tid + it * 512;
        int r = idx >> 4, c = idx & 15;
        cpa16(aU + (uint32_t)(r * AST + c * 4) * 4u, rp + r * 16 + c);
    }
    const float4* np = (const float4*)(nod + (size_t)tile * 16384);
    #pragma unroll
    for (int it = 0; it < 2; it++) {
        int idx = tid + it * 512;
        int r = idx >> 3, c = idx & 7;
        cpa16(aU + (uint32_t)(r * AST + 64 + c * 4) * 4u, np + r * 32 + c);
    }
}
// half1: k 96..191 = nod[32..127]
__device__ __forceinline__ void stage_h1(uint32_t aU, const float* __restrict__ nod,
                                         int tile, int tid) {
    const float4* np = (const float4*)(nod + (size_t)tile * 16384);
    #pragma unroll
    for (int it = 0; it < 6; it++) {
        int idx = tid + it * 512;
        int r = idx / 24, c = idx - r * 24;
        cpa16(aU + (uint32_t)(r * AST + c * 4) * 4u, np + r * 32 + 8 + c);
    }
}
__device__ __forceinline__ void stage_x(uint32_t xU, const float* __restrict__ x,
                                        int tile, int par, int tid) {
    if (tid < 256)
        cpa16(xU + (uint32_t)(par * 1024 + tid * 4) * 4u,
              (const float4*)(x + (size_t)tile * 1024) + tid);
}

// ---- in-place fp32 -> tf32 pass over one A half buffer (3200 float4 incl. pads) ----
__device__ __forceinline__ void cvt_pass(float* buf, int tid) {
    #pragma unroll
    for (int it = 0; it < 6; it++) {
        float4* p = (float4*)buf + tid + it * 512;
        float4 v = *p;
        uint32_t* d = (uint32_t*)p;
        d[0] = cvt_tf32(v.x); d[1] = cvt_tf32(v.y);
        d[2] = cvt_tf32(v.z); d[3] = cvt_tf32(v.w);
    }
    if (tid < 128) {
        float4* p = (float4*)buf + 3072 + tid;
        float4 v = *p;
        uint32_t* d = (uint32_t*)p;
        d[0] = cvt_tf32(v.x); d[1] = cvt_tf32(v.y);
        d[2] = cvt_tf32(v.z); d[3] = cvt_tf32(v.w);
    }
}

// ---- GEMM over one K-half (96): warp tile 32x32, A pre-converted, W pair-permuted ----
__device__ __forceinline__ void compute_half(float acc[2][4][4],
                                             const float* __restrict__ aBuf,
                                             const float* __restrict__ sW,
                                             int h, int wm, int wn, int g, int t4) {
    const uint32_t* aBase = (const uint32_t*)(aBuf + (wm * 32 + g) * AST + t4);
    const uint32_t* bBase = (const uint32_t*)(sW + (wn * 32 + g) * WST + h * 96 + 2 * t4);
    #pragma unroll
    for (int kk = 0; kk < 96; kk += 8) {
        uint32_t bf0[4], bf1[4];
        #pragma unroll
        for (int j = 0; j < 4; j++) {
            uint2 bp = *(const uint2*)(bBase + j * (8 * WST) + kk);
            bf0[j] = bp.x; bf1[j] = bp.y;
        }
        #pragma unroll
        for (int i = 0; i < 2; i++) {
            const uint32_t* p = aBase + i * (16 * AST) + kk;
            uint32_t a0 = p[0];
            uint32_t a1 = p[8 * AST];
            uint32_t a2 = p[4];
            uint32_t a3 = p[8 * AST + 4];
            #pragma unroll
            for (int j = 0; j < 4; j++)
                mma_tf32(acc[i][j], a0, a1, a2, a3, bf0[j], bf1[j]);
        }
    }
}

__global__ __launch_bounds__(512, 1)
void nei_attention_p512(const float* __restrict__ x,
                        const float* __restrict__ x_nei_rel,
                        const float* __restrict__ x_nei_node,
                        const float* __restrict__ W1_w,
                        const float* __restrict__ W1_b,
                        float* __restrict__ out)
{
    extern __shared__ float smem[];
    const uint32_t sb = smem_u32(smem);
    float* sW    = smem + OFF_W;
    float* sA0   = smem + OFF_A0;
    float* sA1   = smem + OFF_A1;
    float* sX    = smem + OFF_X;
    float* sPart = smem + OFF_PART;
    float* sAl   = smem + OFF_AL;
    float* sE    = smem + OFF_E;
    float* sBia  = smem + OFF_BIA;
    const uint32_t aU0 = sb + OFF_A0 * 4, aU1 = sb + OFF_A1 * 4, xU = sb + OFF_X * 4;

    const int tid = threadIdx.x;
    const int wid = tid >> 5, lid = tid & 31;
    const int g = lid >> 2, t4 = lid & 3;
    const int wm = wid >> 2, wn = wid & 3;      // 4 x 4 warp grid, warp tile 32x32
    const int bid = blockIdx.x;

    // ---- stage W once: tf32, pair-permuted (k, k+4 adjacent) ----
    {
        const float4* Wv = (const float4*)W1_w;    // [128 d][192 k]
        #pragma unroll
        for (int it = 0; it < 12; it++) {
            int idx = tid + it * 512;
            int dd = idx / 48, c = idx - dd * 48;
            float4 v = Wv[idx];
            // k0 = 4c; block = (c>>1)*8; within-block pos = (c&1) + 2*m
            uint32_t* dp = (uint32_t*)(sW + dd * WST + (c >> 1) * 8 + (c & 1));
            dp[0] = cvt_tf32(v.x);
            dp[2] = cvt_tf32(v.y);
            dp[4] = cvt_tf32(v.z);
            dp[6] = cvt_tf32(v.w);
        }
        if (tid < 128) sBia[tid] = W1_b[tid];
    }

    // ---- prologue ----
    stage_h0(aU0, x_nei_rel, x_nei_node, bid, tid);
    stage_x(xU, x, bid, 0, tid);
    cp_commit();

    int par = 0;
    for (int tile = bid; tile < NTILES; tile += NCTAS) {
        float acc[2][4][4];
        #pragma unroll
        for (int i = 0; i < 2; i++)
            #pragma unroll
            for (int j = 0; j < 4; j++)
                #pragma unroll
                for (int q = 0; q < 4; q++) acc[i][j][q] = 0.f;

        // -------- half 0 --------
        cp_wait_all();
        __syncthreads();                         // h0 raw landed (and W on iter 0)
        stage_h1(aU1, x_nei_node, tile, tid);    // prefetch h1
        cp_commit();
        cvt_pass(sA0, tid);                      // in-place fp32 -> tf32
        __syncthreads();
        compute_half(acc, sA0, sW, 0, wm, wn, g, t4);

        // -------- half 1 --------
        cp_wait_all();
        __syncthreads();                         // h1 raw landed
        {
            int tn = tile + NCTAS;
            if (tn < NTILES) {
                stage_h0(aU0, x_nei_rel, x_nei_node, tn, tid);
                stage_x(xU, x, tn, par ^ 1, tid);
            }
        }
        cp_commit();
        cvt_pass(sA1, tid);
        __syncthreads();
        compute_half(acc, sA1, sW, 1, wm, wn, g, t4);

        // -------- epilogue: attention from registers --------
        const float* xb = sX + par * 1024;
        #pragma unroll
        for (int i = 0; i < 2; i++) {
            float lo = 0.f, hi = 0.f;
            int node = wm * 2 + i;
            #pragma unroll
            for (int j = 0; j < 4; j++) {
                const float2 xv = *(const float2*)(xb + node * 128 + wn * 32 + j * 8 + 2 * t4);
                lo += xv.x * acc[i][j][0] + xv.y * acc[i][j][1];
                hi += xv.x * acc[i][j][2] + xv.y * acc[i][j][3];
            }
            lo += shflx(lo, 1); lo += shflx(lo, 2);
            hi += shflx(hi, 1); hi += shflx(hi, 2);
            if (t4 == 0) {
                int r = wm * 32 + i * 16 + g;
                sPart[wn * 128 + r]     = lo;
                sPart[wn * 128 + r + 8] = hi;
            }
        }
        __syncthreads();
        float e = 0.f;
        if (tid < 128) {
            sAl[tid] = (sPart[tid] + sPart[128 + tid] + sPart[256 + tid] + sPart[384 + tid])
                       * 0.08838834764831845f;   // 1/sqrt(128)
        }
        __syncthreads();
        if (tid < 128) {
            int base = tid & ~15;
            float m = -1e30f;
            #pragma unroll
            for (int s = 0; s < 16; s++) m = fmaxf(m, sAl[base + s]);
            e = expf(sAl[tid] - m);
            sE[tid] = e;
        }
        __syncthreads();
        if (tid < 128) {
            int base = tid & ~15;
            float den = 0.f;
            #pragma unroll
            for (int s = 0; s < 16; s++) den += sE[base + s];
            sAl[tid] = e / den;
        }
        __syncthreads();

        // out = sum_s alpha*C + bias (sum alpha = 1)
        float* outp = out + (size_t)tile * 1024;
        #pragma unroll
        for (int i = 0; i < 2; i++) {
            int r = wm * 32 + i * 16 + g;
            float alo = sAl[r], ahi = sAl[r + 8];
            int node = wm * 2 + i;
            #pragma unroll
            for (int j = 0; j < 4; j++) {
                float o0 = alo * acc[i][j][0] + ahi * acc[i][j][2];
                float o1 = alo * acc[i][j][1] + ahi * acc[i][j][3];
                o0 += shflx(o0, 4); o0 += shflx(o0, 8); o0 += shflx(o0, 16);
                o1 += shflx(o1, 4); o1 += shflx(o1, 8); o1 += shflx(o1, 16);
                if (lid < 4) {
                    int col = wn * 32 + j * 8 + 2 * t4;
                    float2 w;
                    w.x = o0 + sBia[col];
                    w.y = o1 + sBia[col + 1];
                    *(float2*)(outp + node * 128 + col) = w;
                }
            }
        }
        par ^= 1;
    }
}

extern "C" void kernel_launch(void* const* d_in, const int* in_sizes, int n_in,
                              void* d_out, int out_size)
{
    const float* x          = (const float*)d_in[0];
    const float* x_nei_rel  = (const float*)d_in[1];
    const float* x_nei_node = (const float*)d_in[2];
    const float* W1_w       = (const float*)d_in[3];
    const float* W1_b       = (const float*)d_in[4];
    float* out = (float*)d_out;

    cudaFuncSetAttribute(nei_attention_p512,
                         cudaFuncAttributeMaxDynamicSharedMemorySize, SMEM_BYTES);

    nei_attention_p512<<<NCTAS, 512, SMEM_BYTES>>>(x, x_nei_rel, x_nei_node, W1_w, W1_b, out);
}

// round 6
// speedup vs baseline: 1.4355x; 1.4355x over previous
#include <cuda_runtime.h>
#include <cstdint>

// NeiAttention persistent fp16 mma.sync (m16n8k16, fp32 accum), 512-thread CTAs.
// B=512,N=32,S=16,EF=64,NF=D=128,K=192. tile = 128 GEMM rows.
// W resident as fp16; A: cp.async raw fp32 double-buffered -> fp16 frag buffers (cvt pass);
// ldmatrix fragment loads; register-only attention epilogue.

#define NTILES 2048
#define NCTAS  148
#define RST    100    // raw A row stride (fp32 words)
#define FST    52     // fp16 A row stride (32-bit words; 104 halves, 208 B)
#define WSTW   100    // W fp16 row stride (32-bit words; 200 halves, 400 B)

// smem layout (32-bit words)
#define OFF_WH   0        // 128*100 = 12800 (W fp16)
#define OFF_R0   12800    // 128*100 raw fp32 half-tile
#define OFF_R1   25600    // 12800
#define OFF_F0   38400    // 128*52 = 6656 (fp16 A half)
#define OFF_F1   45056    // 6656
#define OFF_X    51712    // 2 x 1024
#define OFF_PART 53760    // 512
#define OFF_AL   54272    // 128
#define OFF_E    54400    // 128
#define OFF_BIA  54528    // 128
#define SMEM_WORDS 54656
#define SMEM_BYTES (SMEM_WORDS * 4)   // 218,624 B

__device__ __forceinline__ uint32_t smem_u32(const void* p) {
    uint32_t a;
    asm("{ .reg .u64 t; cvta.to.shared.u64 t, %1; cvt.u32.u64 %0, t; }" : "=r"(a) : "l"(p));
    return a;
}
__device__ __forceinline__ uint32_t pack_f16x2(float lo, float hi) {
    uint32_t r;
    asm("cvt.rn.f16x2.f32 %0, %1, %2;" : "=r"(r) : "f"(hi), "f"(lo));  // d.lo=convert(b)
    return r;
}
__device__ __forceinline__ void ldsm4(uint32_t r[4], uint32_t addr) {
    asm volatile("ldmatrix.sync.aligned.m8n8.x4.shared.b16 {%0,%1,%2,%3}, [%4];"
                 : "=r"(r[0]), "=r"(r[1]), "=r"(r[2]), "=r"(r[3]) : "r"(addr));
}
__device__ __forceinline__ void mma_f16(float d[4], const uint32_t a[4],
                                        uint32_t b0, uint32_t b1) {
    asm volatile(
        "mma.sync.aligned.m16n8k16.row.col.f32.f16.f16.f32 "
        "{%0,%1,%2,%3}, {%4,%5,%6,%7}, {%8,%9}, {%0,%1,%2,%3};"
        : "+f"(d[0]), "+f"(d[1]), "+f"(d[2]), "+f"(d[3])
        : "r"(a[0]), "r"(a[1]), "r"(a[2]), "r"(a[3]), "r"(b0), "r"(b1));
}
__device__ __forceinline__ void cpa16(uint32_t dst, const void* src) {
    asm volatile("cp.async.cg.shared.global [%0], [%1], 16;" :: "r"(dst), "l"(src));
}
__device__ __forceinline__ void cp_commit() { asm volatile("cp.async.commit_group;" ::: "memory"); }
__device__ __forceinline__ void cp_wait_all() { asm volatile("cp.async.wait_group 0;" ::: "memory"); }
__device__ __forceinline__ float shflx(float v, int m) { return __shfl_xor_sync(0xffffffffu, v, m); }

// ---- raw fp32 staging via cp.async ----
// half0: k 0..95 = rel[0..63] + nod[0..31]
__device__ __forceinline__ void stage_h0(uint32_t aU, const float* __restrict__ rel,
                                         const float* __restrict__ nod, int tile, int tid) {
    const float4* rp = (const float4*)(rel + (size_t)tile * 8192);
    #pragma unroll
    for (int it = 0; it < 4; it++) {
        int idx = tid + it * 512;
        int r = idx >> 4, c = idx & 15;
        cpa16(aU + (uint32_t)(r * RST + c * 4) * 4u, rp + r * 16 + c);
    }
    const float4* np = (const float4*)(nod + (size_t)tile * 16384);
    #pragma unroll
    for (int it = 0; it < 2; it++) {
        int idx = tid + it * 512;
        int r = idx >> 3, c = idx & 7;
        cpa16(aU + (uint32_t)(r * RST + 64 + c * 4) * 4u, np + r * 32 + c);
    }
}
// half1: k 96..191 = nod[32..127]
__device__ __forceinline__ void stage_h1(uint32_t aU, const float* __restrict__ nod,
                                         int tile, int tid) {
    const float4* np = (const float4*)(nod + (size_t)tile * 16384);
    #pragma unroll
    for (int it = 0; it < 6; it++) {
        int idx = tid + it * 512;
        int r = idx / 24, c = idx - r * 24;
        cpa16(aU + (uint32_t)(r * RST + c * 4) * 4u, np + r * 32 + 8 + c);
    }
}
__device__ __forceinline__ void stage_x(uint32_t xU, const float* __restrict__ x,
                                        int tile, int par, int tid) {
    if (tid < 256)
        cpa16(xU + (uint32_t)(par * 1024 + tid * 4) * 4u,
              (const float4*)(x + (size_t)tile * 1024) + tid);
}

// ---- cvt pass: raw fp32 half-tile -> fp16 frag buffer (128 rows x 96 k) ----
__device__ __forceinline__ void cvt_pass(const float* __restrict__ raw,
                                         uint32_t* __restrict__ f16, int tid) {
    #pragma unroll
    for (int it = 0; it < 6; it++) {
        int idx = tid + it * 512;                 // 0..3071 (= 128 rows * 24 float4)
        int r = idx / 24, c = idx - r * 24;
        float4 v = *(const float4*)(raw + r * RST + c * 4);
        uint2 w;
        w.x = pack_f16x2(v.x, v.y);
        w.y = pack_f16x2(v.z, v.w);
        *(uint2*)(f16 + r * FST + 2 * c) = w;
    }
}

// ---- GEMM over one K-half (96): warp tile 32x32, fp16 m16n8k16 ----
__device__ __forceinline__ void compute_half(float acc[2][4][4],
                                             uint32_t aA0, uint32_t aA1,
                                             uint32_t bA0, uint32_t bA1) {
    #pragma unroll
    for (int ks = 0; ks < 6; ks++) {              // 6 k-steps of 16
        uint32_t a0[4], a1[4], b0[4], b1[4];
        ldsm4(a0, aA0 + ks * 32);
        ldsm4(a1, aA1 + ks * 32);
        ldsm4(b0, bA0 + ks * 32);
        ldsm4(b1, bA1 + ks * 32);
        mma_f16(acc[0][0], a0, b0[0], b0[1]);
        mma_f16(acc[0][1], a0, b0[2], b0[3]);
        mma_f16(acc[0][2], a0, b1[0], b1[1]);
        mma_f16(acc[0][3], a0, b1[2], b1[3]);
        mma_f16(acc[1][0], a1, b0[0], b0[1]);
        mma_f16(acc[1][1], a1, b0[2], b0[3]);
        mma_f16(acc[1][2], a1, b1[0], b1[1]);
        mma_f16(acc[1][3], a1, b1[2], b1[3]);
    }
}

__global__ __launch_bounds__(512, 1)
void nei_attention_f16(const float* __restrict__ x,
                       const float* __restrict__ x_nei_rel,
                       const float* __restrict__ x_nei_node,
                       const float* __restrict__ W1_w,
                       const float* __restrict__ W1_b,
                       float* __restrict__ out)
{
    extern __shared__ float smem[];
    const uint32_t sb = smem_u32(smem);
    uint32_t* sWh  = (uint32_t*)smem + OFF_WH;
    float*    sR0  = smem + OFF_R0;
    float*    sR1  = smem + OFF_R1;
    uint32_t* sF0  = (uint32_t*)smem + OFF_F0;
    uint32_t* sF1  = (uint32_t*)smem + OFF_F1;
    float*    sX   = smem + OFF_X;
    float*    sPart= smem + OFF_PART;
    float*    sAl  = smem + OFF_AL;
    float*    sE   = smem + OFF_E;
    float*    sBia = smem + OFF_BIA;
    const uint32_t rU0 = sb + OFF_R0 * 4, rU1 = sb + OFF_R1 * 4, xU = sb + OFF_X * 4;

    const int tid = threadIdx.x;
    const int wid = tid >> 5, lid = tid & 31;
    const int g = lid >> 2, t4 = lid & 3;
    const int wm = wid >> 2, wn = wid & 3;       // 4x4 warp grid, warp tile 32x32
    const int sel = lid >> 3, lr = lid & 7;
    const int bid = blockIdx.x;

    // ldmatrix per-lane byte addresses (fixed per buffer / half)
    uint32_t aAdr[2][2], bAdr[2][2];
    #pragma unroll
    for (int i = 0; i < 2; i++) {
        uint32_t off = (uint32_t)(wm * 32 + i * 16 + (sel & 1) * 8 + lr) * 208u
                       + (uint32_t)(sel >> 1) * 16u;
        aAdr[0][i] = sb + OFF_F0 * 4 + off;
        aAdr[1][i] = sb + OFF_F1 * 4 + off;
    }
    #pragma unroll
    for (int h = 0; h < 2; h++)
        #pragma unroll
        for (int jp = 0; jp < 2; jp++)
            bAdr[h][jp] = sb + OFF_WH * 4
                          + (uint32_t)(wn * 32 + jp * 16 + (sel >> 1) * 8 + lr) * 400u
                          + (uint32_t)h * 192u + (uint32_t)(sel & 1) * 16u;

    // ---- stage W once as fp16 (natural [n][k] layout) + bias ----
    {
        const float4* Wv = (const float4*)W1_w;   // [128 d][192 k]
        #pragma unroll
        for (int it = 0; it < 12; it++) {
            int idx = tid + it * 512;
            int dd = idx / 48, c = idx - dd * 48;
            float4 v = Wv[idx];
            uint2 w;
            w.x = pack_f16x2(v.x, v.y);
            w.y = pack_f16x2(v.z, v.w);
            *(uint2*)(sWh + dd * WSTW + 2 * c) = w;
        }
        if (tid < 128) sBia[tid] = W1_b[tid];
    }

    // ---- prologue ----
    stage_h0(rU0, x_nei_rel, x_nei_node, bid, tid);
    stage_x(xU, x, bid, 0, tid);
    cp_commit();

    int par = 0;
    for (int tile = bid; tile < NTILES; tile += NCTAS) {
        float acc[2][4][4];
        #pragma unroll
        for (int i = 0; i < 2; i++)
            #pragma unroll
            for (int j = 0; j < 4; j++)
                #pragma unroll
                for (int q = 0; q < 4; q++) acc[i][j][q] = 0.f;

        // -------- half 0 --------
        cp_wait_all();
        __syncthreads();                          // raw h0 landed (+W on iter 0)
        stage_h1(rU1, x_nei_node, tile, tid);     // prefetch raw h1
        cp_commit();
        cvt_pass(sR0, sF0, tid);                  // fp32 -> fp16 frags
        __syncthreads();
        compute_half(acc, aAdr[0][0], aAdr[0][1], bAdr[0][0], bAdr[0][1]);

        // -------- half 1 --------
        cp_wait_all();
        __syncthreads();                          // raw h1 landed
        {
            int tn = tile + NCTAS;
            if (tn < NTILES) {                    // prefetch next tile's h0 + x
                stage_h0(rU0, x_nei_rel, x_nei_node, tn, tid);
                stage_x(xU, x, tn, par ^ 1, tid);
            }
        }
        cp_commit();
        cvt_pass(sR1, sF1, tid);
        __syncthreads();
        compute_half(acc, aAdr[1][0], aAdr[1][1], bAdr[1][0], bAdr[1][1]);

        // -------- epilogue: attention from registers --------
        const float* xb = sX + par * 1024;
        #pragma unroll
        for (int i = 0; i < 2; i++) {
            float lo = 0.f, hi = 0.f;
            int node = wm * 2 + i;
            #pragma unroll
            for (int j = 0; j < 4; j++) {
                const float2 xv = *(const float2*)(xb + node * 128 + wn * 32 + j * 8 + 2 * t4);
                lo += xv.x * acc[i][j][0] + xv.y * acc[i][j][1];
                hi += xv.x * acc[i][j][2] + xv.y * acc[i][j][3];
            }
            lo += shflx(lo, 1); lo += shflx(lo, 2);
            hi += shflx(hi, 1); hi += shflx(hi, 2);
            if (t4 == 0) {
                int r = wm * 32 + i * 16 + g;
                sPart[wn * 128 + r]     = lo;
                sPart[wn * 128 + r + 8] = hi;
            }
        }
        __syncthreads();
        float e = 0.f;
        if (tid < 128) {
            sAl[tid] = (sPart[tid] + sPart[128 + tid] + sPart[256 + tid] + sPart[384 + tid])
                       * 0.08838834764831845f;    // 1/sqrt(128)
        }
        __syncthreads();
        if (tid < 128) {
            int base = tid & ~15;
            float m = -1e30f;
            #pragma unroll
            for (int s = 0; s < 16; s++) m = fmaxf(m, sAl[base + s]);
            e = expf(sAl[tid] - m);
            sE[tid] = e;
        }
        __syncthreads();
        if (tid < 128) {
            int base = tid & ~15;
            float den = 0.f;
            #pragma unroll
            for (int s = 0; s < 16; s++) den += sE[base + s];
            sAl[tid] = e / den;
        }
        __syncthreads();

        // out = sum_s alpha*C + bias (sum alpha = 1)
        float* outp = out + (size_t)tile * 1024;
        #pragma unroll
        for (int i = 0; i < 2; i++) {
            int r = wm * 32 + i * 16 + g;
            float alo = sAl[r], ahi = sAl[r + 8];
            int node = wm * 2 + i;
            #pragma unroll
            for (int j = 0; j < 4; j++) {
                float o0 = alo * acc[i][j][0] + ahi * acc[i][j][2];
                float o1 = alo * acc[i][j][1] + ahi * acc[i][j][3];
                o0 += shflx(o0, 4); o0 += shflx(o0, 8); o0 += shflx(o0, 16);
                o1 += shflx(o1, 4); o1 += shflx(o1, 8); o1 += shflx(o1, 16);
                if (lid < 4) {
                    int col = wn * 32 + j * 8 + 2 * t4;
                    float2 w;
                    w.x = o0 + sBia[col];
                    w.y = o1 + sBia[col + 1];
                    *(float2*)(outp + node * 128 + col) = w;
                }
            }
        }
        par ^= 1;
    }
}

extern "C" void kernel_launch(void* const* d_in, const int* in_sizes, int n_in,
                              void* d_out, int out_size)
{
    const float* x          = (const float*)d_in[0];
    const float* x_nei_rel  = (const float*)d_in[1];
    const float* x_nei_node = (const float*)d_in[2];
    const float* W1_w       = (const float*)d_in[3];
    const float* W1_b       = (const float*)d_in[4];
    float* out = (float*)d_out;

    cudaFuncSetAttribute(nei_attention_f16,
                         cudaFuncAttributeMaxDynamicSharedMemorySize, SMEM_BYTES);

    nei_attention_f16<<<NCTAS, 512, SMEM_BYTES>>>(x, x_nei_rel, x_nei_node, W1_w, W1_b, out);
}

// round 7
// speedup vs baseline: 1.7204x; 1.1984x over previous
#include <cuda_runtime.h>
#include <cuda_fp16.h>
#include <cstdint>

// NeiAttention, factored 3-kernel form.
// logit[n,s] = (x[n] @ W) . a[n,s]   (x.b term is softmax-invariant -> dropped)
// out[n]     = (sum_s alpha[n,s] a[n,s]) @ W^T + b
// K1: y = x @ W           [16384,128]@[128,192]  fp16 MMA -> g_y (fp32)
// K2: logits/softmax/z    streams A (200MB) once, fp32     -> g_z (fp32)
// K3: out = z @ W^T + b   [16384,192]@[192,128]  fp16 MMA -> out

__device__ float g_y[16384 * 192];
__device__ float g_z[16384 * 192];

__device__ __forceinline__ uint32_t smem_u32(const void* p) {
    uint32_t a;
    asm("{ .reg .u64 t; cvta.to.shared.u64 t, %1; cvt.u32.u64 %0, t; }" : "=r"(a) : "l"(p));
    return a;
}
__device__ __forceinline__ uint32_t pack_f16x2(float lo, float hi) {
    uint32_t r;
    asm("cvt.rn.f16x2.f32 %0, %1, %2;" : "=r"(r) : "f"(hi), "f"(lo));
    return r;
}
__device__ __forceinline__ void ldsm4(uint32_t r[4], uint32_t addr) {
    asm volatile("ldmatrix.sync.aligned.m8n8.x4.shared.b16 {%0,%1,%2,%3}, [%4];"
                 : "=r"(r[0]), "=r"(r[1]), "=r"(r[2]), "=r"(r[3]) : "r"(addr));
}
__device__ __forceinline__ void mma_f16(float d[4], const uint32_t a[4],
                                        uint32_t b0, uint32_t b1) {
    asm volatile(
        "mma.sync.aligned.m16n8k16.row.col.f32.f16.f16.f32 "
        "{%0,%1,%2,%3}, {%4,%5,%6,%7}, {%8,%9}, {%0,%1,%2,%3};"
        : "+f"(d[0]), "+f"(d[1]), "+f"(d[2]), "+f"(d[3])
        : "r"(a[0]), "r"(a[1]), "r"(a[2]), "r"(a[3]), "r"(b0), "r"(b1));
}
__device__ __forceinline__ void cpa16(uint32_t dst, const void* src) {
    asm volatile("cp.async.cg.shared.global [%0], [%1], 16;" :: "r"(dst), "l"(src));
}
__device__ __forceinline__ void cp_commit() { asm volatile("cp.async.commit_group;" ::: "memory"); }
template <int N>
__device__ __forceinline__ void cp_wait() { asm volatile("cp.async.wait_group %0;" :: "n"(N) : "memory"); }
__device__ __forceinline__ float shflx(float v, int m) { return __shfl_xor_sync(0xffffffffu, v, m); }

// ============================ K1: y = x @ W ============================
// A = x rows (fp16, K=128), B = W^T as Wt[192][128] fp16. grid 128 x 512thr.
#define K1_XHW  68        // x smem row stride in 32-bit words (136 halves, 272 B)
#define K1_XH   0         // 128*68 = 8704 w
#define K1_WT   8704      // 192*68 = 13056 w
#define K1_WORDS 21760
#define K1_BYTES (K1_WORDS * 4)

__global__ __launch_bounds__(512, 1)
void k1_y(const float* __restrict__ x, const float* __restrict__ W1_w)
{
    extern __shared__ float sm[];
    const uint32_t sb = smem_u32(sm);
    const int tid = threadIdx.x;
    const int wid = tid >> 5, lid = tid & 31;
    const int g = lid >> 2, t4 = lid & 3;
    const int sel = lid >> 3, lr = lid & 7;
    const int wm = wid >> 2, wn = wid & 3;      // warp tile 32 x 48

    // stage x tile (128 rows) as fp16
    {
        const float4* xp = (const float4*)(x + (size_t)blockIdx.x * 128 * 128);
        #pragma unroll
        for (int it = 0; it < 8; it++) {
            int idx = tid + it * 512;           // = r*32 + c
            int r = idx >> 5, c = idx & 31;
            float4 v = xp[idx];
            uint2 w;
            w.x = pack_f16x2(v.x, v.y);
            w.y = pack_f16x2(v.z, v.w);
            *(uint2*)((uint32_t*)sm + K1_XH + r * K1_XHW + 2 * c) = w;
        }
    }
    // stage W transposed: Wt[k'][d] = W[d][k'], fp16
    {
        __half* wt = (__half*)((uint32_t*)sm + K1_WT);
        const float4* Wv = (const float4*)W1_w;      // [128 d][192 k']
        #pragma unroll
        for (int it = 0; it < 12; it++) {
            int idx = tid + it * 512;
            int d = idx / 48, c = idx - d * 48;
            float4 v = Wv[idx];
            wt[(4 * c + 0) * 136 + d] = __float2half(v.x);
            wt[(4 * c + 1) * 136 + d] = __float2half(v.y);
            wt[(4 * c + 2) * 136 + d] = __float2half(v.z);
            wt[(4 * c + 3) * 136 + d] = __float2half(v.w);
        }
    }
    __syncthreads();

    uint32_t aA[2], bA[3];
    #pragma unroll
    for (int i = 0; i < 2; i++)
        aA[i] = sb + K1_XH * 4 + (uint32_t)(wm * 32 + i * 16 + (sel & 1) * 8 + lr) * 272u
                + (uint32_t)(sel >> 1) * 16u;
    #pragma unroll
    for (int jp = 0; jp < 3; jp++)
        bA[jp] = sb + K1_WT * 4 + (uint32_t)(wn * 48 + jp * 16 + (sel >> 1) * 8 + lr) * 272u
                 + (uint32_t)(sel & 1) * 16u;

    float acc[2][6][4];
    #pragma unroll
    for (int i = 0; i < 2; i++)
        #pragma unroll
        for (int j = 0; j < 6; j++)
            #pragma unroll
            for (int q = 0; q < 4; q++) acc[i][j][q] = 0.f;

    #pragma unroll
    for (int ks = 0; ks < 8; ks++) {            // K = 128
        uint32_t a0[4], a1[4], b[3][4];
        ldsm4(a0, aA[0] + ks * 32);
        ldsm4(a1, aA[1] + ks * 32);
        ldsm4(b[0], bA[0] + ks * 32);
        ldsm4(b[1], bA[1] + ks * 32);
        ldsm4(b[2], bA[2] + ks * 32);
        #pragma unroll
        for (int jp = 0; jp < 3; jp++) {
            mma_f16(acc[0][2 * jp],     a0, b[jp][0], b[jp][1]);
            mma_f16(acc[0][2 * jp + 1], a0, b[jp][2], b[jp][3]);
            mma_f16(acc[1][2 * jp],     a1, b[jp][0], b[jp][1]);
            mma_f16(acc[1][2 * jp + 1], a1, b[jp][2], b[jp][3]);
        }
    }

    // write y (fp32)
    #pragma unroll
    for (int i = 0; i < 2; i++) {
        int row = blockIdx.x * 128 + wm * 32 + i * 16 + g;
        #pragma unroll
        for (int j = 0; j < 6; j++) {
            int col = wn * 48 + j * 8 + 2 * t4;
            float2 w0 = { acc[i][j][0], acc[i][j][1] };
            float2 w1 = { acc[i][j][2], acc[i][j][3] };
            *(float2*)(g_y + (size_t)row * 192 + col)       = w0;
            *(float2*)(g_y + (size_t)(row + 8) * 192 + col) = w1;
        }
    }
}

// ============== K2: logits, softmax, z = sum alpha*a  (pure fp32 streaming) ==============
#define K2_AST  196       // A smem row stride (fp32 words), 784 B
#define K2_SA   0         // 128*196 = 25088 w
#define K2_SY   25088     // 8*192 = 1536 w
#define K2_SP   26624     // 256
#define K2_AL   26880     // 128
#define K2_SE   27008     // 128
#define K2_WORDS 27136
#define K2_BYTES (K2_WORDS * 4)   // 108,544 B -> 2 CTAs/SM

__global__ __launch_bounds__(256, 2)
void k2_attn(const float* __restrict__ x_nei_rel,
             const float* __restrict__ x_nei_node)
{
    extern __shared__ float sm[];
    const uint32_t sb = smem_u32(sm);
    float* sA  = sm + K2_SA;
    float* sY  = sm + K2_SY;
    float* sP  = sm + K2_SP;
    float* sAl = sm + K2_AL;
    float* sE  = sm + K2_SE;
    const uint32_t aU = sb + K2_SA * 4, yU = sb + K2_SY * 4;

    const int tid = threadIdx.x;
    const int b = blockIdx.y, nc = blockIdx.x;
    const size_t row0  = (size_t)b * 512 + (size_t)nc * 128;
    const int    nbase = b * 32 + nc * 8;

    // ---- group 0: rel (k 0..63) + node k 64..95 + y rows ----
    {
        const float4* rp = (const float4*)(x_nei_rel + row0 * 64);
        #pragma unroll
        for (int it = 0; it < 8; it++) {
            int idx = tid + it * 256;            // 2048
            int r = idx >> 4, c = idx & 15;
            cpa16(aU + (uint32_t)(r * K2_AST + c * 4) * 4u, rp + r * 16 + c);
        }
        const float4* np = (const float4*)(x_nei_node + row0 * 128);
        #pragma unroll
        for (int it = 0; it < 4; it++) {
            int idx = tid + it * 256;            // 1024
            int r = idx >> 3, c = idx & 7;
            cpa16(aU + (uint32_t)(r * K2_AST + 64 + c * 4) * 4u, np + r * 32 + c);
        }
        #pragma unroll
        for (int it = 0; it < 2; it++) {
            int idx = tid + it * 256;
            if (idx < 384)
                cpa16(yU + (uint32_t)idx * 16u, g_y + (size_t)nbase * 192 + idx * 4);
        }
        cp_commit();
        // ---- group 1: node k 96..191 ----
        #pragma unroll
        for (int it = 0; it < 12; it++) {
            int idx = tid + it * 256;            // 3072
            int r = idx / 24, c = idx - r * 24;
            cpa16(aU + (uint32_t)(r * K2_AST + 96 + c * 4) * 4u, np + r * 32 + 8 + c);
        }
        cp_commit();
    }

    // ---- dot phase 0 (k 0..95) ----
    const int r = tid >> 1, h = tid & 1;
    float s = 0.f;
    cp_wait<1>();
    __syncthreads();
    {
        const float* ar = sA + r * K2_AST + h * 48;
        const float* yr = sY + (r >> 4) * 192 + h * 48;
        #pragma unroll
        for (int k = 0; k < 48; k++) s += ar[k] * yr[k];
    }
    // ---- dot phase 1 (k 96..191) ----
    cp_wait<0>();
    __syncthreads();
    {
        const float* ar = sA + r * K2_AST + 96 + h * 48;
        const float* yr = sY + (r >> 4) * 192 + 96 + h * 48;
        #pragma unroll
        for (int k = 0; k < 48; k++) s += ar[k] * yr[k];
    }
    s += shflx(s, 1);
    if (h == 0) sAl[r] = s * 0.08838834764831845f;   // 1/sqrt(128)
    __syncthreads();

    // ---- softmax over S=16 per node ----
    float e = 0.f;
    if (tid < 128) {
        int base = tid & ~15;
        float m = -1e30f;
        #pragma unroll
        for (int q = 0; q < 16; q++) m = fmaxf(m, sAl[base + q]);
        e = __expf(sAl[tid] - m);
        sE[tid] = e;
    }
    __syncthreads();
    if (tid < 128) {
        int base = tid & ~15;
        float den = 0.f;
        #pragma unroll
        for (int q = 0; q < 16; q++) den += sE[base + q];
        sAl[tid] = e / den;                      // alpha
    }
    __syncthreads();

    // ---- z[node][dim] = sum_s alpha * a ----
    #pragma unroll
    for (int p = 0; p < 6; p++) {
        int u = tid + 256 * p;                   // 0..1535
        int node = u / 192;
        int dim  = u - node * 192;
        const float* ap = sA + (node * 16) * K2_AST + dim;
        const float* al = sAl + node * 16;
        float z = 0.f;
        #pragma unroll
        for (int q = 0; q < 16; q++) z += al[q] * ap[q * K2_AST];
        g_z[(size_t)(nbase + node) * 192 + dim] = z;
    }
}

// ============================ K3: out = z @ W^T + b ============================
// A = z rows fp16 (K=192), B = W natural [128][192] fp16. grid 128 x 512thr.
#define K3_ST   100       // row stride in 32-bit words (200 halves, 400 B)
#define K3_ZH   0         // 128*100 = 12800 w
#define K3_WH   12800     // 128*100 = 12800 w
#define K3_WORDS 25600
#define K3_BYTES (K3_WORDS * 4)   // 102,400 B

__global__ __launch_bounds__(512, 1)
void k3_out(const float* __restrict__ W1_w,
            const float* __restrict__ W1_b,
            float* __restrict__ out)
{
    extern __shared__ float sm[];
    const uint32_t sb = smem_u32(sm);
    const int tid = threadIdx.x;
    const int wid = tid >> 5, lid = tid & 31;
    const int g = lid >> 2, t4 = lid & 3;
    const int sel = lid >> 3, lr = lid & 7;
    const int wm = wid >> 2, wn = wid & 3;      // warp tile 32 x 32

    // stage z rows (fp32 -> fp16)
    {
        const float4* zp = (const float4*)(g_z + (size_t)blockIdx.x * 128 * 192);
        #pragma unroll
        for (int it = 0; it < 12; it++) {
            int idx = tid + it * 512;            // = r*48 + c
            int rr = idx / 48, c = idx - rr * 48;
            float4 v = zp[idx];
            uint2 w;
            w.x = pack_f16x2(v.x, v.y);
            w.y = pack_f16x2(v.z, v.w);
            *(uint2*)((uint32_t*)sm + K3_ZH + rr * K3_ST + 2 * c) = w;
        }
    }
    // stage W (natural [d][k]) fp16
    {
        const float4* Wv = (const float4*)W1_w;
        #pragma unroll
        for (int it = 0; it < 12; it++) {
            int idx = tid + it * 512;
            int d = idx / 48, c = idx - d * 48;
            float4 v = Wv[idx];
            uint2 w;
            w.x = pack_f16x2(v.x, v.y);
            w.y = pack_f16x2(v.z, v.w);
            *(uint2*)((uint32_t*)sm + K3_WH + d * K3_ST + 2 * c) = w;
        }
    }
    __syncthreads();

    uint32_t aA[2], bA[2];
    #pragma unroll
    for (int i = 0; i < 2; i++)
        aA[i] = sb + K3_ZH * 4 + (uint32_t)(wm * 32 + i * 16 + (sel & 1) * 8 + lr) * 400u
                + (uint32_t)(sel >> 1) * 16u;
    #pragma unroll
    for (int jp = 0; jp < 2; jp++)
        bA[jp] = sb + K3_WH * 4 + (uint32_t)(wn * 32 + jp * 16 + (sel >> 1) * 8 + lr) * 400u
                 + (uint32_t)(sel & 1) * 16u;

    float acc[2][4][4];
    #pragma unroll
    for (int i = 0; i < 2; i++)
        #pragma unroll
        for (int j = 0; j < 4; j++)
            #pragma unroll
            for (int q = 0; q < 4; q++) acc[i][j][q] = 0.f;

    #pragma unroll
    for (int ks = 0; ks < 12; ks++) {           // K = 192
        uint32_t a0[4], a1[4], b0[4], b1[4];
        ldsm4(a0, aA[0] + ks * 32);
        ldsm4(a1, aA[1] + ks * 32);
        ldsm4(b0, bA[0] + ks * 32);
        ldsm4(b1, bA[1] + ks * 32);
        mma_f16(acc[0][0], a0, b0[0], b0[1]);
        mma_f16(acc[0][1], a0, b0[2], b0[3]);
        mma_f16(acc[0][2], a0, b1[0], b1[1]);
        mma_f16(acc[0][3], a0, b1[2], b1[3]);
        mma_f16(acc[1][0], a1, b0[0], b0[1]);
        mma_f16(acc[1][1], a1, b0[2], b0[3]);
        mma_f16(acc[1][2], a1, b1[0], b1[1]);
        mma_f16(acc[1][3], a1, b1[2], b1[3]);
    }

    // out = acc + bias
    #pragma unroll
    for (int i = 0; i < 2; i++) {
        int row = blockIdx.x * 128 + wm * 32 + i * 16 + g;
        #pragma unroll
        for (int j = 0; j < 4; j++) {
            int col = wn * 32 + j * 8 + 2 * t4;
            float b0 = __ldg(W1_b + col), b1 = __ldg(W1_b + col + 1);
            float2 w0 = { acc[i][j][0] + b0, acc[i][j][1] + b1 };
            float2 w1 = { acc[i][j][2] + b0, acc[i][j][3] + b1 };
            *(float2*)(out + (size_t)row * 128 + col)       = w0;
            *(float2*)(out + (size_t)(row + 8) * 128 + col) = w1;
        }
    }
}

extern "C" void kernel_launch(void* const* d_in, const int* in_sizes, int n_in,
                              void* d_out, int out_size)
{
    const float* x          = (const float*)d_in[0];
    const float* x_nei_rel  = (const float*)d_in[1];
    const float* x_nei_node = (const float*)d_in[2];
    const float* W1_w       = (const float*)d_in[3];
    const float* W1_b       = (const float*)d_in[4];
    float* out = (float*)d_out;

    cudaFuncSetAttribute(k1_y,    cudaFuncAttributeMaxDynamicSharedMemorySize, K1_BYTES);
    cudaFuncSetAttribute(k2_attn, cudaFuncAttributeMaxDynamicSharedMemorySize, K2_BYTES);
    cudaFuncSetAttribute(k3_out,  cudaFuncAttributeMaxDynamicSharedMemorySize, K3_BYTES);

    k1_y<<<128, 512, K1_BYTES>>>(x, W1_w);
    k2_attn<<<dim3(4, 512), 256, K2_BYTES>>>(x_nei_rel, x_nei_node);
    k3_out<<<128, 512, K3_BYTES>>>(W1_w, W1_b, out);
}

// round 8
// speedup vs baseline: 1.9088x; 1.1095x over previous
#include <cuda_runtime.h>
#include <cuda_fp16.h>
#include <cstdint>

// NeiAttention, factored 3-kernel form (round 8).
// K1: y = x @ W            fp16 MMA, B via ldmatrix.trans (no scatter transpose)
// K2: logits/softmax/z     streams A once (fp32), writes z as fp16
// K3: out = z @ W^T + b    fp16 MMA, z staged by straight cp.async copy

__device__ float  g_y[16384 * 192];
__device__ __half g_z16[16384 * 192];

__device__ __forceinline__ uint32_t smem_u32(const void* p) {
    uint32_t a;
    asm("{ .reg .u64 t; cvta.to.shared.u64 t, %1; cvt.u32.u64 %0, t; }" : "=r"(a) : "l"(p));
    return a;
}
__device__ __forceinline__ uint32_t pack_f16x2(float lo, float hi) {
    uint32_t r;
    asm("cvt.rn.f16x2.f32 %0, %1, %2;" : "=r"(r) : "f"(hi), "f"(lo));
    return r;
}
__device__ __forceinline__ void ldsm4(uint32_t r[4], uint32_t addr) {
    asm volatile("ldmatrix.sync.aligned.m8n8.x4.shared.b16 {%0,%1,%2,%3}, [%4];"
                 : "=r"(r[0]), "=r"(r[1]), "=r"(r[2]), "=r"(r[3]) : "r"(addr));
}
__device__ __forceinline__ void ldsm4t(uint32_t r[4], uint32_t addr) {
    asm volatile("ldmatrix.sync.aligned.m8n8.x4.trans.shared.b16 {%0,%1,%2,%3}, [%4];"
                 : "=r"(r[0]), "=r"(r[1]), "=r"(r[2]), "=r"(r[3]) : "r"(addr));
}
__device__ __forceinline__ void mma_f16(float d[4], const uint32_t a[4],
                                        uint32_t b0, uint32_t b1) {
    asm volatile(
        "mma.sync.aligned.m16n8k16.row.col.f32.f16.f16.f32 "
        "{%0,%1,%2,%3}, {%4,%5,%6,%7}, {%8,%9}, {%0,%1,%2,%3};"
        : "+f"(d[0]), "+f"(d[1]), "+f"(d[2]), "+f"(d[3])
        : "r"(a[0]), "r"(a[1]), "r"(a[2]), "r"(a[3]), "r"(b0), "r"(b1));
}
__device__ __forceinline__ void cpa16(uint32_t dst, const void* src) {
    asm volatile("cp.async.cg.shared.global [%0], [%1], 16;" :: "r"(dst), "l"(src));
}
__device__ __forceinline__ void cp_commit() { asm volatile("cp.async.commit_group;" ::: "memory"); }
template <int N>
__device__ __forceinline__ void cp_wait() { asm volatile("cp.async.wait_group %0;" :: "n"(N) : "memory"); }
__device__ __forceinline__ float shflx(float v, int m) { return __shfl_xor_sync(0xffffffffu, v, m); }

// ============================ K1: y = x @ W ============================
// 256 CTAs x 64 rows, 256 thr (warp grid 2x4, warp tile 32x48).
// A = x rows fp16 (stride 272B). B = W natural [d][k'] fp16 (stride 400B), trans-ldmatrix.
#define K1_XH   0         // 64*68  = 4352 w
#define K1_WH   4352      // 128*100 = 12800 w
#define K1_WORDS 17152
#define K1_BYTES (K1_WORDS * 4)   // 68,608 B

__global__ __launch_bounds__(256, 2)
void k1_y(const float* __restrict__ x, const float* __restrict__ W1_w)
{
    extern __shared__ float sm[];
    const uint32_t sb = smem_u32(sm);
    const int tid = threadIdx.x;
    const int wid = tid >> 5, lid = tid & 31;
    const int g = lid >> 2, t4 = lid & 3;
    const int sel = lid >> 3, lr = lid & 7;
    const int wm = wid >> 2, wn = wid & 3;

    // stage x tile (64 rows, fp16, stride 68 words)
    {
        const float4* xp = (const float4*)(x + (size_t)blockIdx.x * 64 * 128);
        #pragma unroll
        for (int it = 0; it < 8; it++) {
            int idx = tid + it * 256;            // r*32 + c
            int r = idx >> 5, c = idx & 31;
            float4 v = xp[idx];
            uint2 w;
            w.x = pack_f16x2(v.x, v.y);
            w.y = pack_f16x2(v.z, v.w);
            *(uint2*)((uint32_t*)sm + K1_XH + r * 68 + 2 * c) = w;
        }
    }
    // stage W natural [d][k'] fp16 (stride 100 words) — coalesced, no transpose
    {
        const float4* Wv = (const float4*)W1_w;  // [128 d][192 k']
        #pragma unroll
        for (int it = 0; it < 24; it++) {
            int idx = tid + it * 256;
            int d = idx / 48, c = idx - d * 48;
            float4 v = Wv[idx];
            uint2 w;
            w.x = pack_f16x2(v.x, v.y);
            w.y = pack_f16x2(v.z, v.w);
            *(uint2*)((uint32_t*)sm + K1_WH + d * 100 + 2 * c) = w;
        }
    }
    __syncthreads();

    // A fragment addrs (non-trans)
    uint32_t aA[2];
    #pragma unroll
    for (int i = 0; i < 2; i++)
        aA[i] = sb + K1_XH * 4 + (uint32_t)(wm * 32 + i * 16 + (sel & 1) * 8 + lr) * 272u
                + (uint32_t)(sel >> 1) * 16u;
    // B fragment addrs (trans): lane -> row d, col-group of 8 k'
    const int drow = (lid & 7) + ((lid >> 3) & 1) * 8;
    const int kgrp = (lid >> 4);                 // 0/1 -> +8 k'
    uint32_t bT[3];
    #pragma unroll
    for (int jp = 0; jp < 3; jp++)
        bT[jp] = sb + K1_WH * 4 + (uint32_t)drow * 400u
                 + (uint32_t)(wn * 48 + jp * 16 + kgrp * 8) * 2u;

    float acc[2][6][4];
    #pragma unroll
    for (int i = 0; i < 2; i++)
        #pragma unroll
        for (int j = 0; j < 6; j++)
            #pragma unroll
            for (int q = 0; q < 4; q++) acc[i][j][q] = 0.f;

    #pragma unroll
    for (int ks = 0; ks < 8; ks++) {             // K = 128 (d), 16 per step
        uint32_t a0[4], a1[4];
        ldsm4(a0, aA[0] + ks * 32);              // +16 halves along d
        ldsm4(a1, aA[1] + ks * 32);
        #pragma unroll
        for (int jp = 0; jp < 3; jp++) {
            uint32_t bt[4];
            ldsm4t(bt, bT[jp] + ks * 6400);      // +16 d-rows * 400 B
            mma_f16(acc[0][2 * jp],     a0, bt[0], bt[1]);
            mma_f16(acc[0][2 * jp + 1], a0, bt[2], bt[3]);
            mma_f16(acc[1][2 * jp],     a1, bt[0], bt[1]);
            mma_f16(acc[1][2 * jp + 1], a1, bt[2], bt[3]);
        }
    }

    #pragma unroll
    for (int i = 0; i < 2; i++) {
        int row = blockIdx.x * 64 + wm * 32 + i * 16 + g;
        #pragma unroll
        for (int j = 0; j < 6; j++) {
            int col = wn * 48 + j * 8 + 2 * t4;
            float2 w0 = { acc[i][j][0], acc[i][j][1] };
            float2 w1 = { acc[i][j][2], acc[i][j][3] };
            *(float2*)(g_y + (size_t)row * 192 + col)       = w0;
            *(float2*)(g_y + (size_t)(row + 8) * 192 + col) = w1;
        }
    }
}

// ============== K2: logits, softmax, z (fp16 out) ==============
#define K2_AST  196
#define K2_SA   0         // 128*196 = 25088 w
#define K2_SY   25088     // 8*192 = 1536 w
#define K2_AL   26624     // 128
#define K2_SE   26752     // 128
#define K2_WORDS 26880
#define K2_BYTES (K2_WORDS * 4)   // 107,520 B -> 2 CTAs/SM

__global__ __launch_bounds__(256, 2)
void k2_attn(const float* __restrict__ x_nei_rel,
             const float* __restrict__ x_nei_node)
{
    extern __shared__ float sm[];
    const uint32_t sb = smem_u32(sm);
    float* sA  = sm + K2_SA;
    float* sY  = sm + K2_SY;
    float* sAl = sm + K2_AL;
    float* sE  = sm + K2_SE;
    const uint32_t aU = sb + K2_SA * 4, yU = sb + K2_SY * 4;

    const int tid = threadIdx.x;
    const int b = blockIdx.y, nc = blockIdx.x;
    const size_t row0  = (size_t)b * 512 + (size_t)nc * 128;
    const int    nbase = b * 32 + nc * 8;

    // group 0: rel (k 0..63) + node k 64..95 + y rows
    {
        const float4* rp = (const float4*)(x_nei_rel + row0 * 64);
        #pragma unroll
        for (int it = 0; it < 8; it++) {
            int idx = tid + it * 256;
            int r = idx >> 4, c = idx & 15;
            cpa16(aU + (uint32_t)(r * K2_AST + c * 4) * 4u, rp + r * 16 + c);
        }
        const float4* np = (const float4*)(x_nei_node + row0 * 128);
        #pragma unroll
        for (int it = 0; it < 4; it++) {
            int idx = tid + it * 256;
            int r = idx >> 3, c = idx & 7;
            cpa16(aU + (uint32_t)(r * K2_AST + 64 + c * 4) * 4u, np + r * 32 + c);
        }
        #pragma unroll
        for (int it = 0; it < 2; it++) {
            int idx = tid + it * 256;
            if (idx < 384)
                cpa16(yU + (uint32_t)idx * 16u, g_y + (size_t)nbase * 192 + idx * 4);
        }
        cp_commit();
        // group 1: node k 96..191
        #pragma unroll
        for (int it = 0; it < 12; it++) {
            int idx = tid + it * 256;
            int r = idx / 24, c = idx - r * 24;
            cpa16(aU + (uint32_t)(r * K2_AST + 96 + c * 4) * 4u, np + r * 32 + 8 + c);
        }
        cp_commit();
    }

    // dots
    const int r = tid >> 1, h = tid & 1;
    float s = 0.f;
    cp_wait<1>();
    __syncthreads();
    {
        const float* ar = sA + r * K2_AST + h * 48;
        const float* yr = sY + (r >> 4) * 192 + h * 48;
        #pragma unroll
        for (int k = 0; k < 48; k++) s += ar[k] * yr[k];
    }
    cp_wait<0>();
    __syncthreads();
    {
        const float* ar = sA + r * K2_AST + 96 + h * 48;
        const float* yr = sY + (r >> 4) * 192 + 96 + h * 48;
        #pragma unroll
        for (int k = 0; k < 48; k++) s += ar[k] * yr[k];
    }
    s += shflx(s, 1);
    if (h == 0) sAl[r] = s * 0.08838834764831845f;   // 1/sqrt(128)
    __syncthreads();

    // softmax over S=16
    float e = 0.f;
    if (tid < 128) {
        int base = tid & ~15;
        float m = -1e30f;
        #pragma unroll
        for (int q = 0; q < 16; q++) m = fmaxf(m, sAl[base + q]);
        e = __expf(sAl[tid] - m);
        sE[tid] = e;
    }
    __syncthreads();
    if (tid < 128) {
        int base = tid & ~15;
        float den = 0.f;
        #pragma unroll
        for (int q = 0; q < 16; q++) den += sE[base + q];
        sAl[tid] = e / den;
    }
    __syncthreads();

    // z[node][dim-pair] = sum_s alpha * a  -> fp16
    #pragma unroll
    for (int p = 0; p < 3; p++) {
        int u = tid + 256 * p;                   // 0..767 = node*96 + dimpair
        int node = u / 96;
        int dp   = u - node * 96;
        const float* ap = sA + (node * 16) * K2_AST + 2 * dp;
        const float* al = sAl + node * 16;
        float z0 = 0.f, z1 = 0.f;
        #pragma unroll
        for (int q = 0; q < 16; q++) {
            float2 av = *(const float2*)(ap + q * K2_AST);
            float  a  = al[q];
            z0 += a * av.x;
            z1 += a * av.y;
        }
        *(uint32_t*)(g_z16 + (size_t)(nbase + node) * 192 + 2 * dp) = pack_f16x2(z0, z1);
    }
}

// ============================ K3: out = z @ W^T + b ============================
// 256 CTAs x 64 rows, 256 thr (warp grid 2x4, warp tile 32x32).
#define K3_ZH   0         // 64*100 = 6400 w
#define K3_WH   6400      // 128*100 = 12800 w
#define K3_WORDS 19200
#define K3_BYTES (K3_WORDS * 4)   // 76,800 B

__global__ __launch_bounds__(256, 2)
void k3_out(const float* __restrict__ W1_w,
            const float* __restrict__ W1_b,
            float* __restrict__ out)
{
    extern __shared__ float sm[];
    const uint32_t sb = smem_u32(sm);
    const int tid = threadIdx.x;
    const int wid = tid >> 5, lid = tid & 31;
    const int g = lid >> 2, t4 = lid & 3;
    const int sel = lid >> 3, lr = lid & 7;
    const int wm = wid >> 2, wn = wid & 3;

    // stage z rows (already fp16): straight cp.async copy
    {
        const __half* zp = g_z16 + (size_t)blockIdx.x * 64 * 192;
        #pragma unroll
        for (int it = 0; it < 6; it++) {
            int idx = tid + it * 256;            // 0..1535: r*24 + c (16B chunks)
            int r = idx / 24, c = idx - r * 24;
            cpa16(sb + K3_ZH * 4 + (uint32_t)(r * 100 + c * 4) * 4u, zp + r * 192 + c * 8);
        }
        cp_commit();
    }
    // stage W natural [d][k] fp16
    {
        const float4* Wv = (const float4*)W1_w;
        #pragma unroll
        for (int it = 0; it < 24; it++) {
            int idx = tid + it * 256;
            int d = idx / 48, c = idx - d * 48;
            float4 v = Wv[idx];
            uint2 w;
            w.x = pack_f16x2(v.x, v.y);
            w.y = pack_f16x2(v.z, v.w);
            *(uint2*)((uint32_t*)sm + K3_WH + d * 100 + 2 * c) = w;
        }
    }
    cp_wait<0>();
    __syncthreads();

    uint32_t aA[2], bA[2];
    #pragma unroll
    for (int i = 0; i < 2; i++)
        aA[i] = sb + K3_ZH * 4 + (uint32_t)(wm * 32 + i * 16 + (sel & 1) * 8 + lr) * 400u
                + (uint32_t)(sel >> 1) * 16u;
    #pragma unroll
    for (int jp = 0; jp < 2; jp++)
        bA[jp] = sb + K3_WH * 4 + (uint32_t)(wn * 32 + jp * 16 + (sel >> 1) * 8 + lr) * 400u
                 + (uint32_t)(sel & 1) * 16u;

    float acc[2][4][4];
    #pragma unroll
    for (int i = 0; i < 2; i++)
        #pragma unroll
        for (int j = 0; j < 4; j++)
            #pragma unroll
            for (int q = 0; q < 4; q++) acc[i][j][q] = 0.f;

    #pragma unroll
    for (int ks = 0; ks < 12; ks++) {            // K = 192
        uint32_t a0[4], a1[4], b0[4], b1[4];
        ldsm4(a0, aA[0] + ks * 32);
        ldsm4(a1, aA[1] + ks * 32);
        ldsm4(b0, bA[0] + ks * 32);
        ldsm4(b1, bA[1] + ks * 32);
        mma_f16(acc[0][0], a0, b0[0], b0[1]);
        mma_f16(acc[0][1], a0, b0[2], b0[3]);
        mma_f16(acc[0][2], a0, b1[0], b1[1]);
        mma_f16(acc[0][3], a0, b1[2], b1[3]);
        mma_f16(acc[1][0], a1, b0[0], b0[1]);
        mma_f16(acc[1][1], a1, b0[2], b0[3]);
        mma_f16(acc[1][2], a1, b1[0], b1[1]);
        mma_f16(acc[1][3], a1, b1[2], b1[3]);
    }

    #pragma unroll
    for (int i = 0; i < 2; i++) {
        int row = blockIdx.x * 64 + wm * 32 + i * 16 + g;
        #pragma unroll
        for (int j = 0; j < 4; j++) {
            int col = wn * 32 + j * 8 + 2 * t4;
            float b0 = __ldg(W1_b + col), b1 = __ldg(W1_b + col + 1);
            float2 w0 = { acc[i][j][0] + b0, acc[i][j][1] + b1 };
            float2 w1 = { acc[i][j][2] + b0, acc[i][j][3] + b1 };
            *(float2*)(out + (size_t)row * 128 + col)       = w0;
            *(float2*)(out + (size_t)(row + 8) * 128 + col) = w1;
        }
    }
}

extern "C" void kernel_launch(void* const* d_in, const int* in_sizes, int n_in,
                              void* d_out, int out_size)
{
    const float* x          = (const float*)d_in[0];
    const float* x_nei_rel  = (const float*)d_in[1];
    const float* x_nei_node = (const float*)d_in[2];
    const float* W1_w       = (const float*)d_in[3];
    const float* W1_b       = (const float*)d_in[4];
    float* out = (float*)d_out;

    cudaFuncSetAttribute(k1_y,    cudaFuncAttributeMaxDynamicSharedMemorySize, K1_BYTES);
    cudaFuncSetAttribute(k2_attn, cudaFuncAttributeMaxDynamicSharedMemorySize, K2_BYTES);
    cudaFuncSetAttribute(k3_out,  cudaFuncAttributeMaxDynamicSharedMemorySize, K3_BYTES);

    k1_y<<<256, 256, K1_BYTES>>>(x, W1_w);
    k2_attn<<<dim3(4, 512), 256, K2_BYTES>>>(x_nei_rel, x_nei_node);
    k3_out<<<256, 256, K3_BYTES>>>(W1_w, W1_b, out);
}